// round 14
// baseline (speedup 1.0000x reference)
#include <cuda_runtime.h>

#define DD     4096
#define KB     128
#define TROWS  16384

#define NBUILD 128
#define NK1    (TROWS / 16)          // 1024
#define NK2    (TROWS / 8)           // 2048
#define NGRID  (NBUILD + NK1 + NK2)  // 3200

__device__ int            g_offsets[KB + 1];
__device__ unsigned short g_perm[DD];
__device__ float4         g_Yt[(TROWS / 4) * KB];
__device__ int            g_done  = 0;        // builders finished (0..128)
__device__ int            g_pdone = 0;        // k1 CTAs that consumed perm
__device__ int            g_flag[NK1];        // 0 -> 2 (ready) -> 0 (consumed x2)

__device__ __forceinline__ int swz(int j) { return j ^ ((j >> 3) & 7); }

__device__ __forceinline__ void fma2(unsigned long long& d,
                                     unsigned long long a, unsigned long long b) {
    asm("fma.rn.f32x2 %0, %1, %2, %0;" : "+l"(d) : "l"(a), "l"(b));
}
__device__ __forceinline__ unsigned long long pack2(float q) {
    unsigned long long r;
    asm("mov.b64 %0, {%1, %1};" : "=l"(r) : "r"(__float_as_uint(q)));
    return r;
}
__device__ __forceinline__ float lo2(unsigned long long v) {
    return __uint_as_float((unsigned)v);
}
__device__ __forceinline__ float hi2(unsigned long long v) {
    return __uint_as_float((unsigned)(v >> 32));
}

// smem layout (union of phases)
#define OFF_PERM  65536
#define OFF_OFFS  (OFF_PERM + 8192)
#define SMEM_BYTES (OFF_OFFS + 4 * (KB + 1))
// k2 overlay: s_y4 @0 (4KB), s_part @4096 (16KB), s_qm @20480 (4KB)

__global__ void __launch_bounds__(512, 2)
vq_fused(const float* __restrict__ x, const float* __restrict__ qv,
         const int* __restrict__ assign, const float* __restrict__ bias,
         float* __restrict__ out) {
    extern __shared__ char smem[];
    __shared__ int s_wcnt[16], s_wlt[16];

    const int tid = threadIdx.x, lane = tid & 31, w = tid >> 5;
    const int bid = blockIdx.x;

    // =======================================================================
    // PHASE A: builders (bid < 128). CTA b builds bin b's CSR segment.
    // =======================================================================
    if (bid < NBUILD) {
        unsigned char* s_a = (unsigned char*)smem;
        const int b = bid;

        for (int j = tid; j < DD; j += 512)
            s_a[j] = (unsigned char)(assign[j] & 127);
        __syncthreads();

        // warp w handles js [256w, 256w+256)
        int hit = 0, lt = 0;
        #pragma unroll
        for (int i = 0; i < 8; i++) {
            int a = (int)s_a[256 * w + 32 * i + lane];
            hit += (a == b); lt += (a < b);
        }
        #pragma unroll
        for (int d = 16; d >= 1; d >>= 1) {
            hit += __shfl_xor_sync(0xffffffffu, hit, d);
            lt  += __shfl_xor_sync(0xffffffffu, lt, d);
        }
        if (lane == 0) { s_wcnt[w] = hit; s_wlt[w] = lt; }
        __syncthreads();

        int binbase = 0, warpbase = 0;
        #pragma unroll
        for (int u = 0; u < 16; u++) {
            binbase += s_wlt[u];
            if (u < w) warpbase += s_wcnt[u];
        }
        if (tid == 0) {
            g_offsets[b] = binbase;
            if (b == 0) g_offsets[KB] = DD;
        }

        int e = warpbase;
        #pragma unroll
        for (int i = 0; i < 8; i++) {
            int j = 256 * w + 32 * i + lane;
            bool h = ((int)s_a[j] == b);
            unsigned m = __ballot_sync(0xffffffffu, h);
            if (h) g_perm[binbase + e + __popc(m & ((1u << lane) - 1u))] =
                       (unsigned short)j;
            e += __popc(m);
        }
        __syncthreads();
        if (tid == 0) { __threadfence(); atomicAdd(&g_done, 1); }
        return;
    }

    // =======================================================================
    // PHASE B: k1 (128 <= bid < 128+1024). Y = per-bin sums, 16 rows/CTA.
    // =======================================================================
    if (bid < NBUILD + NK1) {
        float4*         s_x4   = (float4*)smem;
        unsigned short* s_perm = (unsigned short*)(smem + OFF_PERM);
        int*            s_off  = (int*)(smem + OFF_OFFS);

        const int kidx = bid - NBUILD;
        const int t0 = kidx * 16;
        const float4* x4 = (const float4*)x;

        // prefetch batch 0 BEFORE waiting on builders (hides build latency)
        float4 v[4][2];
        #pragma unroll
        for (int r = 0; r < 4; r++) {
            v[r][0] = x4[(size_t)(t0 + r) * 1024 + 2 * tid];
            v[r][1] = x4[(size_t)(t0 + r) * 1024 + 2 * tid + 1];
        }

        if (tid == 0)
            while (atomicAdd(&g_done, 0) < NBUILD) __nanosleep(200);
        __syncthreads();
        __threadfence();

        for (int i = tid; i < DD / 2; i += 512) {
            unsigned pr = ((const unsigned*)g_perm)[i];
            unsigned o0 = (unsigned)(swz((int)(pr & 0xffffu)) << 4);
            unsigned o1 = (unsigned)(swz((int)(pr >> 16)) << 4);
            ((unsigned*)s_perm)[i] = o0 | (o1 << 16);
        }
        if (tid <= KB) s_off[tid] = g_offsets[tid];
        __syncthreads();

        // perm consumed: last k1 CTA resets the builder flags for next replay
        if (tid == 0) {
            int n = atomicAdd(&g_pdone, 1);
            if (n == NK1 - 1) { atomicExch(&g_done, 0); atomicExch(&g_pdone, 0); }
        }

        const int bin = tid >> 2, sub = tid & 3;
        const int lo = s_off[bin] + sub, hi = s_off[bin + 1];

        #pragma unroll 1
        for (int b = 0; b < 4; b++) {
            const int tb = t0 + 4 * b;

            #pragma unroll
            for (int p = 0; p < 2; p++) {
                s_x4[swz(8 * tid + 4 * p + 0)] = make_float4(v[0][p].x, v[1][p].x, v[2][p].x, v[3][p].x);
                s_x4[swz(8 * tid + 4 * p + 1)] = make_float4(v[0][p].y, v[1][p].y, v[2][p].y, v[3][p].y);
                s_x4[swz(8 * tid + 4 * p + 2)] = make_float4(v[0][p].z, v[1][p].z, v[2][p].z, v[3][p].z);
                s_x4[swz(8 * tid + 4 * p + 3)] = make_float4(v[0][p].w, v[1][p].w, v[2][p].w, v[3][p].w);
            }
            __syncthreads();

            if (b < 3) {
                #pragma unroll
                for (int r = 0; r < 4; r++) {
                    v[r][0] = x4[(size_t)(tb + 4 + r) * 1024 + 2 * tid];
                    v[r][1] = x4[(size_t)(tb + 4 + r) * 1024 + 2 * tid + 1];
                }
            }

            float4 acc = make_float4(0.f, 0.f, 0.f, 0.f);
            const char* bx = (const char*)s_x4;
            for (int s = lo; s < hi; s += 4) {
                float4 xv = *(const float4*)(bx + s_perm[s]);
                acc.x += xv.x; acc.y += xv.y; acc.z += xv.z; acc.w += xv.w;
            }
            #pragma unroll
            for (int d = 2; d >= 1; d >>= 1) {
                acc.x += __shfl_down_sync(0xffffffffu, acc.x, d);
                acc.y += __shfl_down_sync(0xffffffffu, acc.y, d);
                acc.z += __shfl_down_sync(0xffffffffu, acc.z, d);
                acc.w += __shfl_down_sync(0xffffffffu, acc.w, d);
            }
            if (sub == 0) g_Yt[(tb >> 2) * KB + bin] = acc;
            __syncthreads();
        }

        // publish: this CTA's 16 rows of Y are ready (2 consumers)
        if (tid == 0) { __threadfence(); atomicExch(&g_flag[kidx], 2); }
        return;
    }

    // =======================================================================
    // PHASE C: k2 (bid >= 1152). out = (Y @ QV)[a_j] + bias, 8 rows/CTA.
    // 512 thr; thread = (kout, c = k'-quarter); qvr[32] in registers.
    // =======================================================================
    {
        float4* s_y4   = (float4*)smem;               // [2*128]
        float4* s_part = (float4*)(smem + 4096);      // [2][4][128]
        float4* s_qm   = (float4*)(smem + 20480);     // [2][128]

        const int cidx = bid - NBUILD - NK1;
        const int t0 = cidx * 8;
        const int kidx = cidx >> 1;
        const int kout = tid & 127, c = tid >> 7;

        float qvr[32];
        #pragma unroll
        for (int i = 0; i < 32; i++)
            qvr[i] = qv[(c * 32 + i) * KB + kout];

        float4 biasr[2]; unsigned ar[2];
        #pragma unroll
        for (int s = 0; s < 2; s++) {
            int e4 = s * 512 + tid;
            biasr[s] = ((const float4*)bias)[e4];
            int4 a = ((const int4*)assign)[e4];
            ar[s] = (unsigned)(a.x & 127)
                  | ((unsigned)(a.y & 127) << 8)
                  | ((unsigned)(a.z & 127) << 16)
                  | ((unsigned)(a.w & 127) << 24);
        }

        // wait for producer k1 CTA
        if (tid == 0)
            while (atomicAdd(&g_flag[kidx], 0) == 0) __nanosleep(100);
        __syncthreads();
        __threadfence();

        if (tid < 256) s_y4[tid] = g_Yt[(t0 >> 2) * KB + tid];
        __syncthreads();
        if (tid == 0) atomicSub(&g_flag[kidx], 1);   // consumed (self-reset to 0)

        // matvec: 2 groups of 4 rows, quarter k' per thread
        #pragma unroll
        for (int g = 0; g < 2; g++) {
            unsigned long long acc01 = 0ull, acc23 = 0ull;
            const ulonglong2* sy2 = (const ulonglong2*)(s_y4 + g * KB);
            #pragma unroll
            for (int i = 0; i < 32; i++) {
                unsigned long long qd = pack2(qvr[i]);
                ulonglong2 yv = sy2[c * 32 + i];
                fma2(acc01, yv.x, qd);
                fma2(acc23, yv.y, qd);
            }
            s_part[g * 512 + c * 128 + kout] =
                make_float4(lo2(acc01), hi2(acc01), lo2(acc23), hi2(acc23));
        }
        __syncthreads();

        if (tid < 256) {
            int g = tid >> 7, k = tid & 127;
            float4 t = s_part[g * 512 + k];
            #pragma unroll
            for (int u = 1; u < 4; u++) {
                float4 p = s_part[g * 512 + u * 128 + k];
                t.x += p.x; t.y += p.y; t.z += p.z; t.w += p.w;
            }
            s_qm[g * KB + k] = t;
        }
        __syncthreads();

        float4* out4 = (float4*)out;
        #pragma unroll
        for (int g = 0; g < 2; g++) {
            const float4* qm = s_qm + g * KB;
            #pragma unroll
            for (int s = 0; s < 2; s++) {
                unsigned a = ar[s];
                float4 q0 = qm[a & 255];
                float4 q1 = qm[(a >> 8)  & 255];
                float4 q2 = qm[(a >> 16) & 255];
                float4 q3 = qm[a >> 24];
                float4 bb = biasr[s];
                size_t rb = (size_t)(t0 + 4 * g) * 1024 + s * 512 + tid;
                out4[rb]        = make_float4(q0.x + bb.x, q1.x + bb.y, q2.x + bb.z, q3.x + bb.w);
                out4[rb + 1024] = make_float4(q0.y + bb.x, q1.y + bb.y, q2.y + bb.z, q3.y + bb.w);
                out4[rb + 2048] = make_float4(q0.z + bb.x, q1.z + bb.y, q2.z + bb.z, q3.z + bb.w);
                out4[rb + 3072] = make_float4(q0.w + bb.x, q1.w + bb.y, q2.w + bb.z, q3.w + bb.w);
            }
        }
    }
}

extern "C" void kernel_launch(void* const* d_in, const int* in_sizes, int n_in,
                              void* d_out, int out_size) {
    const float* x      = (const float*)d_in[0];
    const float* qv     = (const float*)d_in[1];
    const int*   assign = (const int*)d_in[2];
    const float* bias   = (const float*)d_in[3];
    float*       out    = (float*)d_out;

    (void)cudaFuncSetAttribute(vq_fused,
        cudaFuncAttributeMaxDynamicSharedMemorySize, SMEM_BYTES);

    vq_fused<<<NGRID, 512, SMEM_BYTES>>>(x, qv, assign, bias, out);
}

// round 15
// speedup vs baseline: 1.0509x; 1.0509x over previous
#include <cuda_runtime.h>

#define DD     4096
#define KB     128
#define TROWS  16384

__device__ int            g_offsets[KB + 1];
__device__ unsigned short g_perm[DD];
__device__ float4         g_Yt[(TROWS / 4) * KB];   // [t/4][k] = y rows t..t+3

// staging stride 8: j=8t+q -> swz low3 = q ^ (t&7): conflict-free
__device__ __forceinline__ int swz(int j) { return j ^ ((j >> 3) & 7); }

__device__ __forceinline__ void fma2(unsigned long long& d,
                                     unsigned long long a, unsigned long long b) {
    asm("fma.rn.f32x2 %0, %1, %2, %0;" : "+l"(d) : "l"(a), "l"(b));
}
__device__ __forceinline__ unsigned long long pack2(float q) {
    unsigned long long r;
    asm("mov.b64 %0, {%1, %1};" : "=l"(r) : "r"(__float_as_uint(q)));
    return r;
}
__device__ __forceinline__ float lo2(unsigned long long v) {
    return __uint_as_float((unsigned)v);
}
__device__ __forceinline__ float hi2(unsigned long long v) {
    return __uint_as_float((unsigned)(v >> 32));
}

// ---------------------------------------------------------------------------
// k0 (R11 version): 128 blocks x 32 thr.
// ---------------------------------------------------------------------------
__global__ void k0_build(const int* __restrict__ assign) {
    const int b = blockIdx.x, lane = threadIdx.x;

    int below = 0;
    for (int i = 0; i < DD / 32; i++) {
        int a = assign[i * 32 + lane] & 127;
        below += (a < b);
    }
    #pragma unroll
    for (int d = 16; d >= 1; d >>= 1)
        below += __shfl_xor_sync(0xffffffffu, below, d);
    int base = below;

    if (lane == 0) {
        g_offsets[b] = base;
        if (b == KB - 1) g_offsets[KB] = DD;
    }
    for (int i = 0; i < DD / 32; i++) {
        int j = i * 32 + lane;
        bool hit = ((assign[j] & 127) == b);
        unsigned m = __ballot_sync(0xffffffffu, hit);
        if (hit) g_perm[base + __popc(m & ((1u << lane) - 1u))] = (unsigned short)j;
        base += __popc(m);
    }
}

// ---------------------------------------------------------------------------
// K1 (R11 version, byte-identical): 512 thr, 2 CTA/SM, 16 rows/CTA.
// ---------------------------------------------------------------------------
#define K1_OFF_PERM 65536
#define K1_OFF_OFFS (K1_OFF_PERM + 8192)
#define K1_SMEM     (K1_OFF_OFFS + 4 * (KB + 1))

__global__ void __launch_bounds__(512, 2)
k1_bins(const float* __restrict__ x) {
    extern __shared__ char smem[];
    float4*         s_x4   = (float4*)smem;                         // 64 KB
    unsigned short* s_perm = (unsigned short*)(smem + K1_OFF_PERM); // pre-swz byte offs
    int*            s_off  = (int*)(smem + K1_OFF_OFFS);

    const int tid = threadIdx.x;

    for (int i = tid; i < DD / 2; i += 512) {
        unsigned pr = ((const unsigned*)g_perm)[i];
        unsigned o0 = (unsigned)(swz((int)(pr & 0xffffu)) << 4);
        unsigned o1 = (unsigned)(swz((int)(pr >> 16)) << 4);
        ((unsigned*)s_perm)[i] = o0 | (o1 << 16);
    }
    if (tid <= KB) s_off[tid] = g_offsets[tid];

    const int bin = tid >> 2, sub = tid & 3;
    const float4* x4 = (const float4*)x;
    const int t0 = blockIdx.x * 16;

    float4 v[4][2];
    #pragma unroll
    for (int r = 0; r < 4; r++) {
        v[r][0] = x4[(size_t)(t0 + r) * 1024 + 2 * tid];
        v[r][1] = x4[(size_t)(t0 + r) * 1024 + 2 * tid + 1];
    }

    __syncthreads();
    const int lo = s_off[bin] + sub, hi = s_off[bin + 1];

    #pragma unroll 1
    for (int b = 0; b < 4; b++) {
        const int tb = t0 + 4 * b;

        #pragma unroll
        for (int p = 0; p < 2; p++) {
            s_x4[swz(8 * tid + 4 * p + 0)] = make_float4(v[0][p].x, v[1][p].x, v[2][p].x, v[3][p].x);
            s_x4[swz(8 * tid + 4 * p + 1)] = make_float4(v[0][p].y, v[1][p].y, v[2][p].y, v[3][p].y);
            s_x4[swz(8 * tid + 4 * p + 2)] = make_float4(v[0][p].z, v[1][p].z, v[2][p].z, v[3][p].z);
            s_x4[swz(8 * tid + 4 * p + 3)] = make_float4(v[0][p].w, v[1][p].w, v[2][p].w, v[3][p].w);
        }
        __syncthreads();

        if (b < 3) {
            #pragma unroll
            for (int r = 0; r < 4; r++) {
                v[r][0] = x4[(size_t)(tb + 4 + r) * 1024 + 2 * tid];
                v[r][1] = x4[(size_t)(tb + 4 + r) * 1024 + 2 * tid + 1];
            }
        }

        float4 acc = make_float4(0.f, 0.f, 0.f, 0.f);
        const char* bx = (const char*)s_x4;
        for (int s = lo; s < hi; s += 4) {
            float4 xv = *(const float4*)(bx + s_perm[s]);
            acc.x += xv.x; acc.y += xv.y; acc.z += xv.z; acc.w += xv.w;
        }
        #pragma unroll
        for (int d = 2; d >= 1; d >>= 1) {
            acc.x += __shfl_down_sync(0xffffffffu, acc.x, d);
            acc.y += __shfl_down_sync(0xffffffffu, acc.y, d);
            acc.z += __shfl_down_sync(0xffffffffu, acc.z, d);
            acc.w += __shfl_down_sync(0xffffffffu, acc.w, d);
        }
        if (sub == 0) g_Yt[(tb >> 2) * KB + bin] = acc;
        __syncthreads();
    }
}

// ---------------------------------------------------------------------------
// K2 (R11 + ONE change): qm table 8x replicated + swizzled so the random
// epilogue gather is bank-conflict-free (LDS.128: 10 -> 4 wavefronts).
// ---------------------------------------------------------------------------
__global__ void __launch_bounds__(256, 2)
k2_out(const float* __restrict__ qv, const int* __restrict__ assign,
       const float* __restrict__ bias, float* __restrict__ out) {
    __shared__ float4 s_y4[2 * KB];        // 4 KB
    __shared__ float4 s_qmp[256];          // 4 KB
    __shared__ float4 s_qm4r[KB * 8];      // 16 KB: [k][copy], copies identical

    const int tid = threadIdx.x;
    const int h = tid >> 7, k = tid & 127;
    const int cp = tid & 7;                // reader copy: bank-group = lane&7

    float qvr[64];
    #pragma unroll
    for (int i = 0; i < 64; i++)
        qvr[i] = qv[(h * 64 + i) * KB + k];

    float4 biasr[4]; unsigned ar[4];
    #pragma unroll
    for (int i = 0; i < 4; i++) {
        int e4 = i * 256 + tid;
        biasr[i] = ((const float4*)bias)[e4];
        int4 a = ((const int4*)assign)[e4];
        ar[i] = (unsigned)(a.x & 127)
              | ((unsigned)(a.y & 127) << 8)
              | ((unsigned)(a.z & 127) << 16)
              | ((unsigned)(a.w & 127) << 24);
    }

    const int t0 = blockIdx.x * 8;
    s_y4[tid] = g_Yt[(t0 >> 2) * KB + tid];
    __syncthreads();

    float4* out4 = (float4*)out;

    #pragma unroll 1
    for (int g = 0; g < 2; g++) {
        const int tb = t0 + 4 * g;

        unsigned long long acc01 = 0ull, acc23 = 0ull;
        const ulonglong2* sy2 = (const ulonglong2*)(s_y4 + g * KB);
        #pragma unroll
        for (int i = 0; i < 64; i++) {
            unsigned long long qd = pack2(qvr[i]);
            ulonglong2 yv = sy2[h * 64 + i];     // warp-broadcast
            fma2(acc01, yv.x, qd);
            fma2(acc23, yv.y, qd);
        }
        s_qmp[tid] = make_float4(lo2(acc01), hi2(acc01), lo2(acc23), hi2(acc23));
        __syncthreads();
        if (tid < KB) {
            float4 a0 = s_qmp[tid], a1 = s_qmp[tid + 128];
            float4 t = make_float4(a0.x + a1.x, a0.y + a1.y,
                                   a0.z + a1.z, a0.w + a1.w);
            // 8 replicated copies, swizzled: slot k*8 + ((u+k)&7) ->
            // per-phase bank-groups (u+tid)&7 are distinct: conflict-free
            #pragma unroll
            for (int u = 0; u < 8; u++)
                s_qm4r[tid * 8 + ((u + tid) & 7)] = t;
        }
        __syncthreads();

        // epilogue: random gather now conflict-free (group = lane&7)
        #pragma unroll
        for (int i = 0; i < 4; i++) {
            unsigned a = ar[i];
            float4 q0 = s_qm4r[(a & 255) * 8 + cp];
            float4 q1 = s_qm4r[((a >> 8)  & 255) * 8 + cp];
            float4 q2 = s_qm4r[((a >> 16) & 255) * 8 + cp];
            float4 q3 = s_qm4r[(a >> 24) * 8 + cp];
            float4 bb = biasr[i];
            size_t rb = (size_t)tb * 1024 + i * 256 + tid;
            out4[rb]        = make_float4(q0.x + bb.x, q1.x + bb.y, q2.x + bb.z, q3.x + bb.w);
            out4[rb + 1024] = make_float4(q0.y + bb.x, q1.y + bb.y, q2.y + bb.z, q3.y + bb.w);
            out4[rb + 2048] = make_float4(q0.z + bb.x, q1.z + bb.y, q2.z + bb.z, q3.z + bb.w);
            out4[rb + 3072] = make_float4(q0.w + bb.x, q1.w + bb.y, q2.w + bb.z, q3.w + bb.w);
        }
        __syncthreads();   // table consumed before next group overwrites
    }
}

extern "C" void kernel_launch(void* const* d_in, const int* in_sizes, int n_in,
                              void* d_out, int out_size) {
    const float* x      = (const float*)d_in[0];
    const float* qv     = (const float*)d_in[1];
    const int*   assign = (const int*)d_in[2];
    const float* bias   = (const float*)d_in[3];
    float*       out    = (float*)d_out;

    (void)cudaFuncSetAttribute(k1_bins,
        cudaFuncAttributeMaxDynamicSharedMemorySize, K1_SMEM);

    k0_build<<<KB, 32>>>(assign);
    k1_bins<<<TROWS / 16, 512, K1_SMEM>>>(x);
    k2_out<<<TROWS / 8, 256>>>(qv, assign, bias, out);
}